// round 11
// baseline (speedup 1.0000x reference)
#include <cuda_runtime.h>
#include <cuda_fp16.h>
#include <cstdint>
#include <math.h>

// Problem dims (fixed)
constexpr int NB = 8;
constexpr int NT = 1024;
constexpr int NC = 1024;
constexpr int NELEM = NB * NT * NC;   // 8M
constexpr int MG = NB * NT;           // 8192 GEMM rows
constexpr int WN = NC * NC;

// scan chunking
constexpr int SG = 64;                // chunks along T
constexpr int SL = NT / SG;           // 16 steps per chunk

// ---------------- scratch (device globals; no runtime alloc) ----------------
__device__ __half g_x3[3 * NELEM];    // xk | xv | xr  (slice 0 reused for rwkv y)
__device__ __half g_kvr[3 * NELEM];   // k | v | r
__device__ __half g_w[4 * WN];        // wk | wv | wr | wo
__device__ float g_Sa[SG * NB * NC], g_Sb[SG * NB * NC];

// ---------------- helpers ----------------
__device__ __forceinline__ uint32_t smem_u32(const void* p) {
    uint32_t a;
    asm("{ .reg .u64 t; cvta.to.shared.u64 t, %1; cvt.u32.u64 %0, t; }"
        : "=r"(a) : "l"(p));
    return a;
}
__device__ __forceinline__ void cp16(uint32_t s, const void* g) {
    asm volatile("cp.async.cg.shared.global [%0], [%1], 16;\n" :: "r"(s), "l"(g));
}
#define CP_COMMIT() asm volatile("cp.async.commit_group;\n" ::: "memory")
#define CP_WAIT1()  asm volatile("cp.async.wait_group 1;\n" ::: "memory")

__device__ __forceinline__ void ldmx4(uint32_t* r, uint32_t addr) {
    asm volatile("ldmatrix.sync.aligned.m8n8.x4.shared.b16 {%0,%1,%2,%3}, [%4];"
                 : "=r"(r[0]), "=r"(r[1]), "=r"(r[2]), "=r"(r[3]) : "r"(addr));
}
// fp16-accumulator HMMA (hypothesis: 2x issue rate vs f32-acc)
__device__ __forceinline__ void mma16816h(uint32_t* c, const uint32_t* a,
                                          uint32_t b0, uint32_t b1) {
    asm volatile(
        "mma.sync.aligned.m16n8k16.row.col.f16.f16.f16.f16 "
        "{%0,%1}, {%2,%3,%4,%5}, {%6,%7}, {%0,%1};"
        : "+r"(c[0]), "+r"(c[1])
        : "r"(a[0]), "r"(a[1]), "r"(a[2]), "r"(a[3]), "r"(b0), "r"(b1));
}

__device__ __forceinline__ unsigned pk2h(float a, float b) {
    __half2 t = __floats2half2_rn(a, b);
    return *reinterpret_cast<unsigned*>(&t);
}
__device__ __forceinline__ void store_cast4h(__half* h, size_t i4,
                                             float a0, float a1, float a2, float a3) {
    reinterpret_cast<uint2*>(h)[i4] = make_uint2(pk2h(a0, a1), pk2h(a2, a3));
}

// ---------------------------------------------------------------------------
// weight cast: all four fp32 [N,K] weights -> fp16, one launch
// ---------------------------------------------------------------------------
__global__ void wcast4_kernel(const float* __restrict__ W0, const float* __restrict__ W1,
                              const float* __restrict__ W2, const float* __restrict__ W3,
                              __half* __restrict__ out) {
    const int j = blockIdx.y;
    const float* W = (j == 0) ? W0 : (j == 1) ? W1 : (j == 2) ? W2 : W3;
    int i = blockIdx.x * blockDim.x + threadIdx.x;
    if (i >= WN / 4) return;
    float4 w = reinterpret_cast<const float4*>(W)[i];
    store_cast4h(out + (size_t)j * WN, i, w.x, w.y, w.z, w.w);
}

// ---------------------------------------------------------------------------
// fused time-shift mix -> xk, xv, xr (fp16)
// ---------------------------------------------------------------------------
__global__ void mix_kernel(const float* __restrict__ x,
                           const float* __restrict__ mk,
                           const float* __restrict__ mv,
                           const float* __restrict__ mr,
                           __half* __restrict__ x3) {
    int i = blockIdx.x * blockDim.x + threadIdx.x;     // float4 idx
    if (i >= NELEM / 4) return;
    const int c4 = i & (NC / 4 - 1);
    const int t  = (i >> 8) & (NT - 1);

    float4 xc = reinterpret_cast<const float4*>(x)[i];
    float4 xp = (t == 0) ? make_float4(0.f, 0.f, 0.f, 0.f)
                         : reinterpret_cast<const float4*>(x)[i - NC / 4];
    float4 k4 = reinterpret_cast<const float4*>(mk)[c4];
    float4 v4 = reinterpret_cast<const float4*>(mv)[c4];
    float4 r4 = reinterpret_cast<const float4*>(mr)[c4];

    float dx0 = xc.x - xp.x, dx1 = xc.y - xp.y, dx2 = xc.z - xp.z, dx3 = xc.w - xp.w;

    store_cast4h(x3, i, fmaf(k4.x, dx0, xp.x), fmaf(k4.y, dx1, xp.y),
                        fmaf(k4.z, dx2, xp.z), fmaf(k4.w, dx3, xp.w));
    store_cast4h(x3 + NELEM, i, fmaf(v4.x, dx0, xp.x), fmaf(v4.y, dx1, xp.y),
                                fmaf(v4.z, dx2, xp.z), fmaf(v4.w, dx3, xp.w));
    store_cast4h(x3 + 2 * (size_t)NELEM, i,
                 fmaf(r4.x, dx0, xp.x), fmaf(r4.y, dx1, xp.y),
                 fmaf(r4.z, dx2, xp.z), fmaf(r4.w, dx3, xp.w));
}

// ---------------------------------------------------------------------------
// fp16 mma.sync GEMM with per-chunk fp16 accumulation + fp32 master acc.
// C[m,n] = sum_k A[m,k] * W[n,k]. CTA tile 128x128x64, 4 warps (64x64),
// 3-stage cp.async pipeline. blockIdx.z = job. 2 CTAs/SM.
// ---------------------------------------------------------------------------
constexpr int LDT = 72;                    // padded smem row stride (halves)
constexpr int TILE_ELE = 128 * LDT;        // 9216 halves = 18432 B
constexpr int NSTAGE = 3;
constexpr int KCH = NC / 64;               // 16 chunks
constexpr int GEMM_SMEM = NSTAGE * 2 * TILE_ELE * 2;   // 110592 B

template<typename OutT>
__global__ void __launch_bounds__(128, 2)
gemm_h(const __half* __restrict__ Ab, const __half* __restrict__ Wb,
       OutT* __restrict__ Cb, size_t strideA, size_t strideW, size_t strideC) {
    extern __shared__ __half smem[];
    const uint32_t sb = smem_u32(smem);
    const int tid = threadIdx.x;
    const int lane = tid & 31;
    const int wid = tid >> 5;        // 0..3
    const int wm = wid & 1;          // M dir (64 rows)
    const int wn = wid >> 1;         // N dir (64 cols)
    const int nTile = blockIdx.x, mTile = blockIdx.y, job = blockIdx.z;

    const char* gA = (const char*)(Ab + job * strideA + (size_t)mTile * 128 * NC);
    const char* gW = (const char*)(Wb + job * strideW + (size_t)nTile * 128 * NC);
    OutT* C = Cb + job * strideC;

    // loader: per tile 1024 x 16B units; u = i*128 + tid -> row=u>>3, colu=u&7
    auto load_chunk = [&](int c, int s) {
        uint32_t st = sb + (uint32_t)s * 2 * TILE_ELE * 2;
        #pragma unroll
        for (int i = 0; i < 8; i++) {
            int u = i * 128 + tid;
            int row = u >> 3, colu = u & 7;
            uint32_t so = (uint32_t)(row * LDT + colu * 8) * 2;
            size_t go = (size_t)row * 2048 + (size_t)(c * 64 + colu * 8) * 2;
            cp16(st + so, gA + go);
            cp16(st + TILE_ELE * 2 + so, gW + go);
        }
        CP_COMMIT();
    };

    load_chunk(0, 0);
    load_chunk(1, 1);

    float acc[4][8][4];
    #pragma unroll
    for (int mt = 0; mt < 4; mt++)
        #pragma unroll
        for (int nt = 0; nt < 8; nt++)
            #pragma unroll
            for (int q = 0; q < 4; q++) acc[mt][nt][q] = 0.f;

    const int lrow = lane & 15;
    const int lcol = (lane >> 4) * 8;

    for (int c = 0; c < KCH; c++) {
        const int s = c % NSTAGE;
        CP_WAIT1();
        __syncthreads();
        if (c + 2 < KCH) load_chunk(c + 2, (c + 2) % NSTAGE);
        else CP_COMMIT();

        const uint32_t st = sb + (uint32_t)s * 2 * TILE_ELE * 2;

        // fp16 chunk accumulators (zeroed each chunk; only 4 fp16 roundings deep)
        uint32_t hc[4][8][2];
        #pragma unroll
        for (int mt = 0; mt < 4; mt++)
            #pragma unroll
            for (int nt = 0; nt < 8; nt++) { hc[mt][nt][0] = 0u; hc[mt][nt][1] = 0u; }

        #pragma unroll
        for (int ks = 0; ks < 4; ks++) {
            const int kc = ks * 16 + lcol;
            uint32_t a[4][4], b[4][4];
            #pragma unroll
            for (int mt = 0; mt < 4; mt++)
                ldmx4(a[mt], st + (uint32_t)((wm * 64 + mt * 16 + lrow) * LDT + kc) * 2);
            #pragma unroll
            for (int pr = 0; pr < 4; pr++)
                ldmx4(b[pr], st + TILE_ELE * 2 +
                             (uint32_t)((wn * 64 + pr * 16 + lrow) * LDT + kc) * 2);
            #pragma unroll
            for (int mt = 0; mt < 4; mt++)
                #pragma unroll
                for (int nt = 0; nt < 8; nt++) {
                    const int pr = nt >> 1, ix = nt & 1;
                    mma16816h(hc[mt][nt], a[mt], b[pr][ix], b[pr][ix + 2]);
                }
        }

        // flush chunk fp16 acc into fp32 master acc
        #pragma unroll
        for (int mt = 0; mt < 4; mt++)
            #pragma unroll
            for (int nt = 0; nt < 8; nt++) {
                float2 f01 = __half22float2(*reinterpret_cast<__half2*>(&hc[mt][nt][0]));
                float2 f23 = __half22float2(*reinterpret_cast<__half2*>(&hc[mt][nt][1]));
                acc[mt][nt][0] += f01.x;
                acc[mt][nt][1] += f01.y;
                acc[mt][nt][2] += f23.x;
                acc[mt][nt][3] += f23.y;
            }
        __syncthreads();
    }

    // epilogue
    const int erow = mTile * 128 + wm * 64 + (lane >> 2);
    const int ecol = nTile * 128 + wn * 64 + (lane & 3) * 2;
    #pragma unroll
    for (int mt = 0; mt < 4; mt++) {
        #pragma unroll
        for (int nt = 0; nt < 8; nt++) {
            OutT* p0 = C + (size_t)(erow + mt * 16) * NC + ecol + nt * 8;
            OutT* p1 = C + (size_t)(erow + mt * 16 + 8) * NC + ecol + nt * 8;
            if (sizeof(OutT) == 4) {
                *reinterpret_cast<float2*>(p0) = make_float2(acc[mt][nt][0], acc[mt][nt][1]);
                *reinterpret_cast<float2*>(p1) = make_float2(acc[mt][nt][2], acc[mt][nt][3]);
            } else {
                *reinterpret_cast<unsigned*>(p0) = pk2h(acc[mt][nt][0], acc[mt][nt][1]);
                *reinterpret_cast<unsigned*>(p1) = pk2h(acc[mt][nt][2], acc[mt][nt][3]);
            }
        }
    }
}

// ---------------------------------------------------------------------------
// chunk-parallel WKV scan (3 passes); k/v/r fp16 (half2: 2 channels/thread)
// ---------------------------------------------------------------------------
__global__ void scan_p1(const __half2* __restrict__ k, const __half2* __restrict__ v,
                        const float* __restrict__ td,
                        float2* __restrict__ Sa, float2* __restrict__ Sb) {
    const int c2 = blockIdx.x * blockDim.x + threadIdx.x;  // 0..NC/2-1
    const int b = blockIdx.y, g = blockIdx.z;
    const float2 tdv = reinterpret_cast<const float2*>(td)[c2];
    const float px = __expf(-__expf(tdv.x));
    const float py = __expf(-__expf(tdv.y));

    size_t idx = ((size_t)b * NT + g * SL) * (NC / 2) + c2;
    float Ax = 0.f, Ay = 0.f, Bx = 0.f, By = 0.f;
    #pragma unroll 8
    for (int t = 0; t < SL; t++, idx += NC / 2) {
        float2 kf = __half22float2(k[idx]);
        float2 vf = __half22float2(v[idx]);
        float ekx = __expf(fminf(kf.x, 60.f));
        float eky = __expf(fminf(kf.y, 60.f));
        Ax = fmaf(px, Ax, ekx * vf.x);
        Ay = fmaf(py, Ay, eky * vf.y);
        Bx = fmaf(px, Bx, ekx);
        By = fmaf(py, By, eky);
    }
    size_t o = ((size_t)g * NB + b) * (NC / 2) + c2;
    Sa[o] = make_float2(Ax, Ay);
    Sb[o] = make_float2(Bx, By);
}

__global__ void scan_p2(const float* __restrict__ td,
                        float* __restrict__ Sa, float* __restrict__ Sb) {
    const int c = blockIdx.x * blockDim.x + threadIdx.x;
    const int b = blockIdx.y;
    const float pl = __expf(-__expf(td[c]) * (float)SL);   // p^SL
    float A = 0.f, Bb = 0.f;
    for (int g = 0; g < SG; g++) {
        size_t o = ((size_t)g * NB + b) * NC + c;
        float ta = Sa[o], tb = Sb[o];
        Sa[o] = A; Sb[o] = Bb;                 // start state for chunk g
        A  = fmaf(pl, A, ta);
        Bb = fmaf(pl, Bb, tb);
    }
}

__global__ void scan_p3(const __half2* __restrict__ k, const __half2* __restrict__ v,
                        const __half2* __restrict__ r, const float* __restrict__ td,
                        const float* __restrict__ tf,
                        const float2* __restrict__ Sa, const float2* __restrict__ Sb,
                        __half2* __restrict__ y) {
    const int c2 = blockIdx.x * blockDim.x + threadIdx.x;
    const int b = blockIdx.y, g = blockIdx.z;
    const float2 tdv = reinterpret_cast<const float2*>(td)[c2];
    const float2 tfv = reinterpret_cast<const float2*>(tf)[c2];
    const float px = __expf(-__expf(tdv.x));
    const float py = __expf(-__expf(tdv.y));
    const float ux = __expf(tfv.x);
    const float uy = __expf(tfv.y);

    size_t o = ((size_t)g * NB + b) * (NC / 2) + c2;
    float2 Af = Sa[o], Bf = Sb[o];
    float Ax = Af.x, Ay = Af.y, Bx = Bf.x, By = Bf.y;

    size_t idx = ((size_t)b * NT + g * SL) * (NC / 2) + c2;
    #pragma unroll 4
    for (int t = 0; t < SL; t++, idx += NC / 2) {
        float2 kf = __half22float2(k[idx]);
        float2 vf = __half22float2(v[idx]);
        float2 rf = __half22float2(r[idx]);
        float ekx = __expf(fminf(kf.x, 60.f));
        float eky = __expf(fminf(kf.y, 60.f));
        float kvx = ekx * vf.x, kvy = eky * vf.y;
        float nx = fmaf(ux, kvx, Ax), ny = fmaf(uy, kvy, Ay);
        float dx = fmaf(ux, ekx, Bx) + 1e-9f, dy = fmaf(uy, eky, By) + 1e-9f;
        float sx = 1.f / (1.f + __expf(-rf.x));
        float sy = 1.f / (1.f + __expf(-rf.y));
        y[idx] = __floats2half2_rn(sx * nx / dx, sy * ny / dy);
        Ax = fmaf(px, Ax, kvx);  Ay = fmaf(py, Ay, kvy);
        Bx = fmaf(px, Bx, ekx);  By = fmaf(py, By, eky);
    }
}

// ---------------------------------------------------------------------------
// launch
// ---------------------------------------------------------------------------
extern "C" void kernel_launch(void* const* d_in, const int* in_sizes, int n_in,
                              void* d_out, int out_size) {
    const float* x  = (const float*)d_in[0];
    const float* td = (const float*)d_in[1];
    const float* tf = (const float*)d_in[2];
    const float* mk = (const float*)d_in[3];
    const float* mv = (const float*)d_in[4];
    const float* mr = (const float*)d_in[5];
    const float* Wk = (const float*)d_in[6];
    const float* Wv = (const float*)d_in[7];
    const float* Wr = (const float*)d_in[8];
    const float* Wo = (const float*)d_in[9];
    float* out = (float*)d_out;

    __half *x3, *kvr, *w;
    float *Sa, *Sb;
    cudaGetSymbolAddress((void**)&x3, g_x3);
    cudaGetSymbolAddress((void**)&kvr, g_kvr);
    cudaGetSymbolAddress((void**)&w, g_w);
    cudaGetSymbolAddress((void**)&Sa, g_Sa);
    cudaGetSymbolAddress((void**)&Sb, g_Sb);

    cudaFuncSetAttribute(gemm_h<__half>,
                         cudaFuncAttributeMaxDynamicSharedMemorySize, GEMM_SMEM);
    cudaFuncSetAttribute(gemm_h<float>,
                         cudaFuncAttributeMaxDynamicSharedMemorySize, GEMM_SMEM);

    // 1) weight casts (one launch)
    wcast4_kernel<<<dim3(WN / 4 / 256, 4), 256>>>(Wk, Wv, Wr, Wo, w);

    // 2) fused time-shift mix -> xk|xv|xr fp16
    mix_kernel<<<NELEM / 4 / 256, 256>>>(x, mk, mv, mr, x3);

    // 3) k/v/r projections, one merged launch (z = job)
    gemm_h<__half><<<dim3(NC / 128, MG / 128, 3), 128, GEMM_SMEM>>>(
        x3, w, kvr, (size_t)NELEM, (size_t)WN, (size_t)NELEM);

    // 4) chunk-parallel WKV scan; y (rwkv) into x3 slice 0 (reuse)
    const __half2* kb = (const __half2*)kvr;
    const __half2* vb = (const __half2*)(kvr + (size_t)NELEM);
    const __half2* rb = (const __half2*)(kvr + 2 * (size_t)NELEM);
    scan_p1<<<dim3(NC / 2 / 128, NB, SG), 128>>>(kb, vb, td,
                                                 (float2*)Sa, (float2*)Sb);
    scan_p2<<<dim3(NC / 256, NB), 256>>>(td, Sa, Sb);
    scan_p3<<<dim3(NC / 2 / 128, NB, SG), 128>>>(kb, vb, rb, td, tf,
                                                 (const float2*)Sa, (const float2*)Sb,
                                                 (__half2*)x3);

    // 5) output projection (fp32 out)
    gemm_h<float><<<dim3(NC / 128, MG / 128, 1), 128, GEMM_SMEM>>>(
        x3, w + 3 * (size_t)WN, out, 0, 0, 0);
}

// round 13
// speedup vs baseline: 1.0520x; 1.0520x over previous
#include <cuda_runtime.h>
#include <cuda_fp16.h>
#include <cstdint>
#include <math.h>

// Problem dims (fixed)
constexpr int NB = 8;
constexpr int NT = 1024;
constexpr int NC = 1024;
constexpr int NELEM = NB * NT * NC;   // 8M
constexpr int MG = NB * NT;           // 8192 GEMM rows
constexpr int WN = NC * NC;

// scan chunking
constexpr int SG = 64;                // chunks along T
constexpr int SL = NT / SG;           // 16 steps per chunk

// ---------------- scratch (device globals; no runtime alloc) ----------------
__device__ __half g_x3[3 * NELEM];    // xk | xv | xr  (slice 0 reused for rwkv y)
__device__ __half g_kvr[3 * NELEM];   // k | v | r
__device__ __half g_w[4 * WN];        // wk | wv | wr | wo
__device__ float g_Sa[SG * NB * NC], g_Sb[SG * NB * NC];

// ---------------- helpers ----------------
__device__ __forceinline__ uint32_t smem_u32(const void* p) {
    uint32_t a;
    asm("{ .reg .u64 t; cvta.to.shared.u64 t, %1; cvt.u32.u64 %0, t; }"
        : "=r"(a) : "l"(p));
    return a;
}
__device__ __forceinline__ void cp16(uint32_t s, const void* g) {
    asm volatile("cp.async.cg.shared.global [%0], [%1], 16;\n" :: "r"(s), "l"(g));
}
#define CP_COMMIT() asm volatile("cp.async.commit_group;\n" ::: "memory")
#define CP_WAIT1()  asm volatile("cp.async.wait_group 1;\n" ::: "memory")

__device__ __forceinline__ void ldmx4(uint32_t* r, uint32_t addr) {
    asm volatile("ldmatrix.sync.aligned.m8n8.x4.shared.b16 {%0,%1,%2,%3}, [%4];"
                 : "=r"(r[0]), "=r"(r[1]), "=r"(r[2]), "=r"(r[3]) : "r"(addr));
}
__device__ __forceinline__ void mma16816(float* c, const uint32_t* a,
                                         uint32_t b0, uint32_t b1) {
    asm volatile(
        "mma.sync.aligned.m16n8k16.row.col.f32.f16.f16.f32 "
        "{%0,%1,%2,%3}, {%4,%5,%6,%7}, {%8,%9}, {%0,%1,%2,%3};"
        : "+f"(c[0]), "+f"(c[1]), "+f"(c[2]), "+f"(c[3])
        : "r"(a[0]), "r"(a[1]), "r"(a[2]), "r"(a[3]), "r"(b0), "r"(b1));
}

__device__ __forceinline__ unsigned pk2h(float a, float b) {
    __half2 t = __floats2half2_rn(a, b);
    return *reinterpret_cast<unsigned*>(&t);
}
__device__ __forceinline__ void store_cast4h(__half* h, size_t i4,
                                             float a0, float a1, float a2, float a3) {
    reinterpret_cast<uint2*>(h)[i4] = make_uint2(pk2h(a0, a1), pk2h(a2, a3));
}

// ---------------------------------------------------------------------------
// weight cast: all four fp32 [N,K] weights -> fp16, one launch
// ---------------------------------------------------------------------------
__global__ void wcast4_kernel(const float* __restrict__ W0, const float* __restrict__ W1,
                              const float* __restrict__ W2, const float* __restrict__ W3,
                              __half* __restrict__ out) {
    const int j = blockIdx.y;
    const float* W = (j == 0) ? W0 : (j == 1) ? W1 : (j == 2) ? W2 : W3;
    int i = blockIdx.x * blockDim.x + threadIdx.x;
    if (i >= WN / 4) return;
    float4 w = reinterpret_cast<const float4*>(W)[i];
    store_cast4h(out + (size_t)j * WN, i, w.x, w.y, w.z, w.w);
}

// ---------------------------------------------------------------------------
// fused time-shift mix -> xk, xv, xr (fp16)
// ---------------------------------------------------------------------------
__global__ void mix_kernel(const float* __restrict__ x,
                           const float* __restrict__ mk,
                           const float* __restrict__ mv,
                           const float* __restrict__ mr,
                           __half* __restrict__ x3) {
    int i = blockIdx.x * blockDim.x + threadIdx.x;     // float4 idx
    if (i >= NELEM / 4) return;
    const int c4 = i & (NC / 4 - 1);
    const int t  = (i >> 8) & (NT - 1);

    float4 xc = reinterpret_cast<const float4*>(x)[i];
    float4 xp = (t == 0) ? make_float4(0.f, 0.f, 0.f, 0.f)
                         : reinterpret_cast<const float4*>(x)[i - NC / 4];
    float4 k4 = reinterpret_cast<const float4*>(mk)[c4];
    float4 v4 = reinterpret_cast<const float4*>(mv)[c4];
    float4 r4 = reinterpret_cast<const float4*>(mr)[c4];

    float dx0 = xc.x - xp.x, dx1 = xc.y - xp.y, dx2 = xc.z - xp.z, dx3 = xc.w - xp.w;

    store_cast4h(x3, i, fmaf(k4.x, dx0, xp.x), fmaf(k4.y, dx1, xp.y),
                        fmaf(k4.z, dx2, xp.z), fmaf(k4.w, dx3, xp.w));
    store_cast4h(x3 + NELEM, i, fmaf(v4.x, dx0, xp.x), fmaf(v4.y, dx1, xp.y),
                                fmaf(v4.z, dx2, xp.z), fmaf(v4.w, dx3, xp.w));
    store_cast4h(x3 + 2 * (size_t)NELEM, i,
                 fmaf(r4.x, dx0, xp.x), fmaf(r4.y, dx1, xp.y),
                 fmaf(r4.z, dx2, xp.z), fmaf(r4.w, dx3, xp.w));
}

// ---------------------------------------------------------------------------
// single-pass fp16 mma.sync GEMM (fp32 accumulators): C[m,n] = sum_k A[m,k]*W[n,k]
// CTA tile 128x128x64, 4 warps (64x64 each), 3-stage cp.async pipeline,
// K-chunk 64 (4 ks-steps per barrier pair). blockIdx.z = job. 2 CTAs/SM.
// ---------------------------------------------------------------------------
constexpr int LDT = 72;                    // padded smem row stride (halves)
constexpr int TILE_ELE = 128 * LDT;        // 9216 halves = 18432 B
constexpr int NSTAGE = 3;
constexpr int KCH = NC / 64;               // 16 chunks
constexpr int GEMM_SMEM = NSTAGE * 2 * TILE_ELE * 2;   // 110592 B

template<typename OutT>
__global__ void __launch_bounds__(128, 2)
gemm_h(const __half* __restrict__ Ab, const __half* __restrict__ Wb,
       OutT* __restrict__ Cb, size_t strideA, size_t strideW, size_t strideC) {
    extern __shared__ __half smem[];
    const uint32_t sb = smem_u32(smem);
    const int tid = threadIdx.x;
    const int lane = tid & 31;
    const int wid = tid >> 5;        // 0..3
    const int wm = wid & 1;          // M dir (64 rows)
    const int wn = wid >> 1;         // N dir (64 cols)
    const int nTile = blockIdx.x, mTile = blockIdx.y, job = blockIdx.z;

    const char* gA = (const char*)(Ab + job * strideA + (size_t)mTile * 128 * NC);
    const char* gW = (const char*)(Wb + job * strideW + (size_t)nTile * 128 * NC);
    OutT* C = Cb + job * strideC;

    // loader: per tile 1024 x 16B units; u = i*128 + tid -> row=u>>3, colu=u&7
    auto load_chunk = [&](int c, int s) {
        uint32_t st = sb + (uint32_t)s * 2 * TILE_ELE * 2;
        #pragma unroll
        for (int i = 0; i < 8; i++) {
            int u = i * 128 + tid;
            int row = u >> 3, colu = u & 7;
            uint32_t so = (uint32_t)(row * LDT + colu * 8) * 2;
            size_t go = (size_t)row * 2048 + (size_t)(c * 64 + colu * 8) * 2;
            cp16(st + so, gA + go);
            cp16(st + TILE_ELE * 2 + so, gW + go);
        }
        CP_COMMIT();
    };

    load_chunk(0, 0);
    load_chunk(1, 1);

    float acc[4][8][4];
    #pragma unroll
    for (int mt = 0; mt < 4; mt++)
        #pragma unroll
        for (int nt = 0; nt < 8; nt++)
            #pragma unroll
            for (int q = 0; q < 4; q++) acc[mt][nt][q] = 0.f;

    const int lrow = lane & 15;
    const int lcol = (lane >> 4) * 8;

    for (int c = 0; c < KCH; c++) {
        const int s = c % NSTAGE;
        CP_WAIT1();
        __syncthreads();
        if (c + 2 < KCH) load_chunk(c + 2, (c + 2) % NSTAGE);
        else CP_COMMIT();

        const uint32_t st = sb + (uint32_t)s * 2 * TILE_ELE * 2;
        #pragma unroll
        for (int ks = 0; ks < 4; ks++) {
            const int kc = ks * 16 + lcol;
            uint32_t a[4][4], b[4][4];
            #pragma unroll
            for (int mt = 0; mt < 4; mt++)
                ldmx4(a[mt], st + (uint32_t)((wm * 64 + mt * 16 + lrow) * LDT + kc) * 2);
            #pragma unroll
            for (int pr = 0; pr < 4; pr++)
                ldmx4(b[pr], st + TILE_ELE * 2 +
                             (uint32_t)((wn * 64 + pr * 16 + lrow) * LDT + kc) * 2);
            #pragma unroll
            for (int mt = 0; mt < 4; mt++)
                #pragma unroll
                for (int nt = 0; nt < 8; nt++) {
                    const int pr = nt >> 1, ix = nt & 1;
                    mma16816(acc[mt][nt], a[mt], b[pr][ix], b[pr][ix + 2]);
                }
        }
        __syncthreads();
    }

    // epilogue
    const int erow = mTile * 128 + wm * 64 + (lane >> 2);
    const int ecol = nTile * 128 + wn * 64 + (lane & 3) * 2;
    #pragma unroll
    for (int mt = 0; mt < 4; mt++) {
        #pragma unroll
        for (int nt = 0; nt < 8; nt++) {
            OutT* p0 = C + (size_t)(erow + mt * 16) * NC + ecol + nt * 8;
            OutT* p1 = C + (size_t)(erow + mt * 16 + 8) * NC + ecol + nt * 8;
            if (sizeof(OutT) == 4) {
                *reinterpret_cast<float2*>(p0) = make_float2(acc[mt][nt][0], acc[mt][nt][1]);
                *reinterpret_cast<float2*>(p1) = make_float2(acc[mt][nt][2], acc[mt][nt][3]);
            } else {
                *reinterpret_cast<unsigned*>(p0) = pk2h(acc[mt][nt][0], acc[mt][nt][1]);
                *reinterpret_cast<unsigned*>(p1) = pk2h(acc[mt][nt][2], acc[mt][nt][3]);
            }
        }
    }
}

// ---------------------------------------------------------------------------
// chunk-parallel WKV scan (3 passes); k/v/r fp16 (half2: 2 channels/thread)
// ---------------------------------------------------------------------------
__global__ void scan_p1(const __half2* __restrict__ k, const __half2* __restrict__ v,
                        const float* __restrict__ td,
                        float2* __restrict__ Sa, float2* __restrict__ Sb) {
    const int c2 = blockIdx.x * blockDim.x + threadIdx.x;  // 0..NC/2-1
    const int b = blockIdx.y, g = blockIdx.z;
    const float2 tdv = reinterpret_cast<const float2*>(td)[c2];
    const float px = __expf(-__expf(tdv.x));
    const float py = __expf(-__expf(tdv.y));

    size_t idx = ((size_t)b * NT + g * SL) * (NC / 2) + c2;
    float Ax = 0.f, Ay = 0.f, Bx = 0.f, By = 0.f;
    #pragma unroll 8
    for (int t = 0; t < SL; t++, idx += NC / 2) {
        float2 kf = __half22float2(k[idx]);
        float2 vf = __half22float2(v[idx]);
        float ekx = __expf(fminf(kf.x, 60.f));
        float eky = __expf(fminf(kf.y, 60.f));
        Ax = fmaf(px, Ax, ekx * vf.x);
        Ay = fmaf(py, Ay, eky * vf.y);
        Bx = fmaf(px, Bx, ekx);
        By = fmaf(py, By, eky);
    }
    size_t o = ((size_t)g * NB + b) * (NC / 2) + c2;
    Sa[o] = make_float2(Ax, Ay);
    Sb[o] = make_float2(Bx, By);
}

__global__ void scan_p2(const float* __restrict__ td,
                        float* __restrict__ Sa, float* __restrict__ Sb) {
    const int c = blockIdx.x * blockDim.x + threadIdx.x;
    const int b = blockIdx.y;
    const float pl = __expf(-__expf(td[c]) * (float)SL);   // p^SL
    float A = 0.f, Bb = 0.f;
    for (int g = 0; g < SG; g++) {
        size_t o = ((size_t)g * NB + b) * NC + c;
        float ta = Sa[o], tb = Sb[o];
        Sa[o] = A; Sb[o] = Bb;                 // start state for chunk g
        A  = fmaf(pl, A, ta);
        Bb = fmaf(pl, Bb, tb);
    }
}

__global__ void scan_p3(const __half2* __restrict__ k, const __half2* __restrict__ v,
                        const __half2* __restrict__ r, const float* __restrict__ td,
                        const float* __restrict__ tf,
                        const float2* __restrict__ Sa, const float2* __restrict__ Sb,
                        __half2* __restrict__ y) {
    const int c2 = blockIdx.x * blockDim.x + threadIdx.x;
    const int b = blockIdx.y, g = blockIdx.z;
    const float2 tdv = reinterpret_cast<const float2*>(td)[c2];
    const float2 tfv = reinterpret_cast<const float2*>(tf)[c2];
    const float px = __expf(-__expf(tdv.x));
    const float py = __expf(-__expf(tdv.y));
    const float ux = __expf(tfv.x);
    const float uy = __expf(tfv.y);

    size_t o = ((size_t)g * NB + b) * (NC / 2) + c2;
    float2 Af = Sa[o], Bf = Sb[o];
    float Ax = Af.x, Ay = Af.y, Bx = Bf.x, By = Bf.y;

    size_t idx = ((size_t)b * NT + g * SL) * (NC / 2) + c2;
    #pragma unroll 4
    for (int t = 0; t < SL; t++, idx += NC / 2) {
        float2 kf = __half22float2(k[idx]);
        float2 vf = __half22float2(v[idx]);
        float2 rf = __half22float2(r[idx]);
        float ekx = __expf(fminf(kf.x, 60.f));
        float eky = __expf(fminf(kf.y, 60.f));
        float kvx = ekx * vf.x, kvy = eky * vf.y;
        float nx = fmaf(ux, kvx, Ax), ny = fmaf(uy, kvy, Ay);
        float dx = fmaf(ux, ekx, Bx) + 1e-9f, dy = fmaf(uy, eky, By) + 1e-9f;
        float sx = 1.f / (1.f + __expf(-rf.x));
        float sy = 1.f / (1.f + __expf(-rf.y));
        y[idx] = __floats2half2_rn(sx * nx / dx, sy * ny / dy);
        Ax = fmaf(px, Ax, kvx);  Ay = fmaf(py, Ay, kvy);
        Bx = fmaf(px, Bx, ekx);  By = fmaf(py, By, eky);
    }
}

// ---------------------------------------------------------------------------
// launch
// ---------------------------------------------------------------------------
extern "C" void kernel_launch(void* const* d_in, const int* in_sizes, int n_in,
                              void* d_out, int out_size) {
    const float* x  = (const float*)d_in[0];
    const float* td = (const float*)d_in[1];
    const float* tf = (const float*)d_in[2];
    const float* mk = (const float*)d_in[3];
    const float* mv = (const float*)d_in[4];
    const float* mr = (const float*)d_in[5];
    const float* Wk = (const float*)d_in[6];
    const float* Wv = (const float*)d_in[7];
    const float* Wr = (const float*)d_in[8];
    const float* Wo = (const float*)d_in[9];
    float* out = (float*)d_out;

    __half *x3, *kvr, *w;
    float *Sa, *Sb;
    cudaGetSymbolAddress((void**)&x3, g_x3);
    cudaGetSymbolAddress((void**)&kvr, g_kvr);
    cudaGetSymbolAddress((void**)&w, g_w);
    cudaGetSymbolAddress((void**)&Sa, g_Sa);
    cudaGetSymbolAddress((void**)&Sb, g_Sb);

    cudaFuncSetAttribute(gemm_h<__half>,
                         cudaFuncAttributeMaxDynamicSharedMemorySize, GEMM_SMEM);
    cudaFuncSetAttribute(gemm_h<float>,
                         cudaFuncAttributeMaxDynamicSharedMemorySize, GEMM_SMEM);

    // 1) weight casts (one launch)
    wcast4_kernel<<<dim3(WN / 4 / 256, 4), 256>>>(Wk, Wv, Wr, Wo, w);

    // 2) fused time-shift mix -> xk|xv|xr fp16
    mix_kernel<<<NELEM / 4 / 256, 256>>>(x, mk, mv, mr, x3);

    // 3) k/v/r projections, one merged launch (z = job)
    gemm_h<__half><<<dim3(NC / 128, MG / 128, 3), 128, GEMM_SMEM>>>(
        x3, w, kvr, (size_t)NELEM, (size_t)WN, (size_t)NELEM);

    // 4) chunk-parallel WKV scan; y (rwkv) into x3 slice 0 (reuse)
    const __half2* kb = (const __half2*)kvr;
    const __half2* vb = (const __half2*)(kvr + (size_t)NELEM);
    const __half2* rb = (const __half2*)(kvr + 2 * (size_t)NELEM);
    scan_p1<<<dim3(NC / 2 / 128, NB, SG), 128>>>(kb, vb, td,
                                                 (float2*)Sa, (float2*)Sb);
    scan_p2<<<dim3(NC / 256, NB), 256>>>(td, Sa, Sb);
    scan_p3<<<dim3(NC / 2 / 128, NB, SG), 128>>>(kb, vb, rb, td, tf,
                                                 (const float2*)Sa, (const float2*)Sb,
                                                 (__half2*)x3);

    // 5) output projection (fp32 out)
    gemm_h<float><<<dim3(NC / 128, MG / 128, 1), 128, GEMM_SMEM>>>(
        x3, w + 3 * (size_t)WN, out, 0, 0, 0);
}